// round 14
// baseline (speedup 1.0000x reference)
#include <cuda_runtime.h>
#include <cuda_fp16.h>
#include <math.h>
#include <stdint.h>

#define BB 2
#define NN 4096
#define DD 512
#define HH 8
#define DHD 64
#define BNROWS (BB*NN)        // 8192
#define QKVC (3*HH*DHD)       // 1536
#define INNER (HH*DHD)        // 512

// Scratch (device globals; no allocations allowed)
__device__ __align__(16) __half g_xh[BNROWS*DD];      // x in fp16
__device__ __align__(16) __half g_wqkvh[DD*QKVC];     // w_qkv in fp16
__device__ __align__(16) __half g_wouth[INNER*DD];    // w_out in fp16
__device__ __align__(16) __half g_qh[BB*HH*NN*DHD];   // [bh][n][64], pre-scaled by 0.125*log2e
__device__ __align__(16) __half g_kh[BB*HH*NN*DHD];   // [bh][n][64]
__device__ __align__(16) __half g_vh[BB*HH*NN*DHD];   // [bh][n][64]
__device__ __align__(16) __half g_atth[BNROWS*INNER]; // attention output fp16 [b][n][h*64+d]
__device__ __align__(16) float g_gates[BNROWS*HH];
__device__ __align__(16) float g_cost[NN*16];
__device__ __align__(16) float g_sint[NN*16];

// inv_freq[j] = 10^(-j/16), j = 0..15
__constant__ float c_invf[16] = {
    1.0000000000f, 0.8659643234f, 0.7498942093f, 0.6493816316f,
    0.5623413252f, 0.4869675252f, 0.4216965034f, 0.3651741273f,
    0.3162277660f, 0.2738419634f, 0.2371373706f, 0.2053525026f,
    0.1778279410f, 0.1539926526f, 0.1333521432f, 0.1154781985f
};

#define QSCALE 0.1803368801111831f   /* 0.125 * log2(e): S comes out in log2 units */
#define SHIFT2 11.541560327111707f   /* 8 * log2(e): static softmax shift */

// ---------------------------------------------------------------------------
// helpers
// ---------------------------------------------------------------------------
__device__ __forceinline__ uint32_t smem_u32(const void* p) {
    uint32_t a;
    asm("{ .reg .u64 t; cvta.to.shared.u64 t, %1; cvt.u32.u64 %0, t; }" : "=r"(a) : "l"(p));
    return a;
}
__device__ __forceinline__ float fexp2(float x) {
    float r; asm("ex2.approx.f32 %0, %1;" : "=f"(r) : "f"(x)); return r;
}
__device__ __forceinline__ uint32_t pack_f16x2(float lo, float hi) {
    uint32_t r; asm("cvt.rn.f16x2.f32 %0, %1, %2;" : "=r"(r) : "f"(hi), "f"(lo)); return r;
}
__device__ __forceinline__ void ldsm4(uint32_t r[4], uint32_t addr) {
    asm volatile("ldmatrix.sync.aligned.m8n8.x4.shared.b16 {%0,%1,%2,%3}, [%4];"
        : "=r"(r[0]), "=r"(r[1]), "=r"(r[2]), "=r"(r[3]) : "r"(addr));
}
__device__ __forceinline__ void ldsm4t(uint32_t r[4], uint32_t addr) {
    asm volatile("ldmatrix.sync.aligned.m8n8.x4.trans.shared.b16 {%0,%1,%2,%3}, [%4];"
        : "=r"(r[0]), "=r"(r[1]), "=r"(r[2]), "=r"(r[3]) : "r"(addr));
}
__device__ __forceinline__ void mma16816(float* c, const uint32_t* a, uint32_t b0, uint32_t b1) {
    asm volatile("mma.sync.aligned.m16n8k16.row.col.f32.f16.f16.f32 "
        "{%0,%1,%2,%3}, {%4,%5,%6,%7}, {%8,%9}, {%0,%1,%2,%3};"
        : "+f"(c[0]), "+f"(c[1]), "+f"(c[2]), "+f"(c[3])
        : "r"(a[0]), "r"(a[1]), "r"(a[2]), "r"(a[3]), "r"(b0), "r"(b1));
}
__device__ __forceinline__ void cp16(uint32_t dst, const void* src) {
    asm volatile("cp.async.cg.shared.global [%0], [%1], 16;" :: "r"(dst), "l"(src));
}
#define CP_COMMIT() asm volatile("cp.async.commit_group;" ::: "memory")
#define CP_WAIT1()  asm volatile("cp.async.wait_group 1;" ::: "memory")

// ---------------------------------------------------------------------------
// K0: fused prep — fp32->fp16 for x, w_qkv, w_out + RoPE tables, one launch
// ---------------------------------------------------------------------------
#define N1_4 (BNROWS*DD/4)    // 1048576
#define N2_4 (DD*QKVC/4)      //  196608
#define N3_4 (INNER*DD/4)     //   65536
#define NCVT (N1_4 + N2_4 + N3_4)
#define NROPE (NN*16)         //   65536

__global__ __launch_bounds__(256) void prep_all(
    const float* __restrict__ x, const float* __restrict__ wq,
    const float* __restrict__ wo)
{
    const int i = blockIdx.x * 256 + threadIdx.x;
    if (i < NCVT) {
        const float* src;
        __half* dst;
        int off;
        if (i < N1_4) { src = x; dst = g_xh; off = i; }
        else if (i < N1_4 + N2_4) { src = wq; dst = g_wqkvh; off = i - N1_4; }
        else { src = wo; dst = g_wouth; off = i - N1_4 - N2_4; }
        float4 v = ((const float4*)src)[off];
        uint2 o;
        o.x = pack_f16x2(v.x, v.y);
        o.y = pack_f16x2(v.z, v.w);
        ((uint2*)dst)[off] = o;
    } else {
        const int idx = i - NCVT;
        if (idx < NROPE) {
            const int n = idx >> 4;
            const int p = idx & 15;
            float s, c;
            sincosf((float)n * c_invf[p], &s, &c);
            g_cost[idx] = c;
            g_sint[idx] = s;
        }
    }
}

// ---------------------------------------------------------------------------
// K2: gates = sigmoid(X @ Wg + bg)  (fp32 — reads harness x directly)
// ---------------------------------------------------------------------------
__global__ __launch_bounds__(256) void gates_kernel(
    const float* __restrict__ X, const float* __restrict__ Wg,
    const float* __restrict__ bg)
{
    const int warp = threadIdx.x >> 5;
    const int lane = threadIdx.x & 31;
    const int row = blockIdx.x * 8 + warp;

    float p[8];
#pragma unroll
    for (int h = 0; h < 8; h++) p[h] = 0.f;

    for (int d = lane; d < DD; d += 32) {
        const float xv = X[(size_t)row*DD + d];
        const float* wr = Wg + (size_t)d*HH;
#pragma unroll
        for (int h = 0; h < 8; h++) p[h] = fmaf(xv, wr[h], p[h]);
    }
#pragma unroll
    for (int h = 0; h < 8; h++) {
#pragma unroll
        for (int off = 16; off > 0; off >>= 1)
            p[h] += __shfl_down_sync(0xffffffffu, p[h], off);
    }
    if (lane == 0) {
#pragma unroll
        for (int h = 0; h < 8; h++) {
            const float z = p[h] + bg[h];
            g_gates[(size_t)row*HH + h] = 1.f / (1.f + expf(-z));
        }
    }
}

// ---------------------------------------------------------------------------
// K1: HMMA GEMM QKV = Xh[8192,512] @ Wh[512,1536] with fused RoPE epilogue.
// BM=128 BN=128 BK=64, 256 threads. Dynamic SMEM 64KB.
// ---------------------------------------------------------------------------
__global__ __launch_bounds__(256, 2) void qkv_hmma()
{
    extern __shared__ __align__(128) __half dsm[];
    const int tid = threadIdx.x;
    const int lane = tid & 31;
    const int w = tid >> 5;
    const int wm = w & 3;
    const int wn = w >> 2;
    const int tileM = blockIdx.y * 128;
    const int tileN = blockIdx.x * 128;

    const uint32_t sa = smem_u32(dsm);
    const uint32_t sbm = sa + 32768;
    const __half* A = g_xh;
    const __half* B = g_wqkvh;

#pragma unroll
    for (int t = 0; t < 2; t++) {
#pragma unroll
        for (int i = 0; i < 4; i++) {
            const int idx = tid + i*256;
            const int r = idx >> 3, c = idx & 7;
            cp16(sa + t*16384 + r*128 + ((c ^ (r & 7))*16),
                 A + (size_t)(tileM + r)*DD + t*64 + c*8);
        }
#pragma unroll
        for (int i = 0; i < 4; i++) {
            const int idx = tid + i*256;
            const int r = idx >> 4, c = idx & 15;
            cp16(sbm + t*16384 + r*256 + ((c ^ (r & 7))*16),
                 B + (size_t)(t*64 + r)*QKVC + tileN + c*8);
        }
        CP_COMMIT();
    }

    float acc[2][8][4];
#pragma unroll
    for (int mi = 0; mi < 2; mi++)
#pragma unroll
        for (int ni = 0; ni < 8; ni++)
#pragma unroll
            for (int i = 0; i < 4; i++) acc[mi][ni][i] = 0.f;

    for (int it = 0; it < DD/64; it++) {
        const int buf = it & 1;
        CP_WAIT1();
        __syncthreads();
        const uint32_t ka = sa + buf*16384;
        const uint32_t kb = sbm + buf*16384;

#pragma unroll
        for (int kk = 0; kk < 4; kk++) {
            uint32_t a[2][4];
            const int g = lane >> 3;
#pragma unroll
            for (int mi = 0; mi < 2; mi++) {
                const int row = wm*32 + mi*16 + (lane & 7) + ((g & 1) << 3);
                const int chunk = kk*2 + (g >> 1);
                ldsm4(a[mi], ka + row*128 + ((chunk ^ (row & 7))*16));
            }
#pragma unroll
            for (int j2 = 0; j2 < 4; j2++) {
                uint32_t bf[4];
                const int row = kk*16 + ((g & 1) << 3) + (lane & 7);
                const int chunk = wn*8 + j2*2 + (g >> 1);
                ldsm4t(bf, kb + row*256 + ((chunk ^ (row & 7))*16));
#pragma unroll
                for (int mi = 0; mi < 2; mi++) {
                    mma16816(acc[mi][2*j2],   a[mi], bf[0], bf[1]);
                    mma16816(acc[mi][2*j2+1], a[mi], bf[2], bf[3]);
                }
            }
        }

        __syncthreads();
        if (it + 2 < DD/64) {
#pragma unroll
            for (int i = 0; i < 4; i++) {
                const int idx = tid + i*256;
                const int r = idx >> 3, c = idx & 7;
                cp16(sa + buf*16384 + r*128 + ((c ^ (r & 7))*16),
                     A + (size_t)(tileM + r)*DD + (it+2)*64 + c*8);
            }
#pragma unroll
            for (int i = 0; i < 4; i++) {
                const int idx = tid + i*256;
                const int r = idx >> 4, c = idx & 15;
                cp16(sbm + buf*16384 + r*256 + ((c ^ (r & 7))*16),
                     B + (size_t)((it+2)*64 + r)*QKVC + tileN + c*8);
            }
        }
        CP_COMMIT();
    }

    // ---- epilogue: RoPE + scatter to fp16 q/k/v ----
#pragma unroll
    for (int mi = 0; mi < 2; mi++) {
        const int r1 = tileM + wm*32 + mi*16 + (lane >> 2);
#pragma unroll
        for (int ni = 0; ni < 8; ni++) {
            const int c0 = tileN + wn*64 + ni*8 + 2*(lane & 3);
            const int which = c0 >> 9;       // 0=q, 1=k, 2=v
            const int rem = c0 & 511;
            const int head = rem >> 6;
            const int dd = rem & 63;         // even
            const int p = (dd >> 1) & 15;
#pragma unroll
            for (int rr = 0; rr < 2; rr++) {
                const int row = r1 + rr*8;
                const int b = row >> 12;
                const int n = row & 4095;
                const float v1 = acc[mi][ni][2*rr];
                const float v2 = acc[mi][ni][2*rr+1];
                const size_t base = (((size_t)(b*HH + head))*NN + n)*DHD + dd;
                if (which == 2) {
                    *(__half2*)(g_vh + base) = __floats2half2_rn(v1, v2);
                } else {
                    const float cs = g_cost[n*16 + p];
                    const float sn = g_sint[n*16 + p];
                    const float o1 = v1*cs - v2*sn;
                    const float o2 = v1*sn + v2*cs;
                    if (which == 0)
                        *(__half2*)(g_qh + base) = __floats2half2_rn(o1*QSCALE, o2*QSCALE);
                    else
                        *(__half2*)(g_kh + base) = __floats2half2_rn(o1, o2);
                }
            }
        }
    }
}

// ---------------------------------------------------------------------------
// K3: HMMA flash attention — 4 warps x 32 query rows, 3-buffer cp.async ring
// with ONE __syncthreads per iteration. Softmax shift folded into S init.
// 48KB static smem, 2 CTAs/SM.
// ---------------------------------------------------------------------------
__global__ __launch_bounds__(128, 2) void flash_hmma()
{
    __shared__ __align__(128) __half smem[6*4096];   // 48 KB: 3 x (K 8KB | V 8KB)

    const int tid = threadIdx.x;
    const int lane = tid & 31;
    const int w = tid >> 5;          // 0..3, each owns 32 query rows
    const int bh = blockIdx.y;
    const int b = bh >> 3;
    const int head = bh & 7;
    const int qt = blockIdx.x;

    const __half* Qg = g_qh + ((size_t)bh*NN + qt*128)*DHD;
    const __half* Kg = g_kh + (size_t)bh*NN*DHD;
    const __half* Vg = g_vh + (size_t)bh*NN*DHD;

    const uint32_t sb = smem_u32(smem);

    // stage Q tile [128x64] (swizzled, into buf0 region), extract A-fragments
#pragma unroll
    for (int i = 0; i < 8; i++) {
        const int idx = tid + i*128;          // 0..1023
        const int row = idx >> 3;
        const int c = idx & 7;
        float4 val = *(const float4*)(Qg + row*DHD + c*8);
        *(float4*)((char*)smem + row*128 + ((c ^ (row & 7))*16)) = val;
    }
    __syncthreads();

    uint32_t qa[2][4][4];
    {
        const int g = lane >> 3;
#pragma unroll
        for (int mi = 0; mi < 2; mi++) {
#pragma unroll
            for (int kk = 0; kk < 4; kk++) {
                const int row = w*32 + mi*16 + (lane & 7) + ((g & 1) << 3);
                const int chunk = kk*2 + (g >> 1);
                ldsm4(qa[mi][kk], sb + row*128 + ((chunk ^ (row & 7))*16));
            }
        }
    }
    __syncthreads();

    // prefetch key-tiles 0,1 into bufs 0,1
#pragma unroll
    for (int t = 0; t < 2; t++) {
#pragma unroll
        for (int i = 0; i < 8; i++) {
            const int idx = tid + i*128;       // 0..1023
            const int isV = idx >> 9;
            const int r = (idx & 511) >> 3;
            const int c = idx & 7;
            const __half* src = (isV ? Vg : Kg) + ((size_t)t*64 + r)*DHD + c*8;
            const uint32_t dst = sb + t*16384 + isV*8192 + r*128 + ((c ^ (r & 7))*16);
            cp16(dst, src);
        }
        CP_COMMIT();
    }

    float oacc[2][8][4];
#pragma unroll
    for (int mi = 0; mi < 2; mi++)
#pragma unroll
        for (int j = 0; j < 8; j++)
#pragma unroll
            for (int i = 0; i < 4; i++) oacc[mi][j][i] = 0.f;
    float lA0 = 0.f, lB0 = 0.f, lA1 = 0.f, lB1 = 0.f;

    int buf = 0;
    for (int it = 0; it < NN/64; it++) {
        __syncthreads();      // all warps done reading buf (it-1)%3
        CP_WAIT1();           // tile it has landed
        // prefetch tile it+2 into buf (it+2)%3 == (it-1)%3 — safe post-barrier
        if (it + 2 < NN/64) {
            const int pbuf = (buf + 2 > 2) ? buf - 1 : buf + 2;
#pragma unroll
            for (int i = 0; i < 8; i++) {
                const int idx = tid + i*128;
                const int isV = idx >> 9;
                const int r = (idx & 511) >> 3;
                const int c = idx & 7;
                const __half* src = (isV ? Vg : Kg) + ((size_t)(it+2)*64 + r)*DHD + c*8;
                const uint32_t dst = sb + pbuf*16384 + isV*8192 + r*128 + ((c ^ (r & 7))*16);
                cp16(dst, src);
            }
        }
        CP_COMMIT();

        const uint32_t kb = sb + buf*16384;
        const uint32_t vb = kb + 8192;

        // ---- fused QK + softmax, j2-outer; shift folded into accum init ----
        uint32_t pa[2][4][4];
        float rA0 = 0.f, rB0 = 0.f, rA1 = 0.f, rB1 = 0.f;
        const int g = lane >> 3;
#pragma unroll
        for (int j2 = 0; j2 < 4; j2++) {
            float s0[2][4], s1[2][4];
#pragma unroll
            for (int mi = 0; mi < 2; mi++)
#pragma unroll
                for (int i = 0; i < 4; i++) { s0[mi][i] = -SHIFT2; s1[mi][i] = -SHIFT2; }
#pragma unroll
            for (int kk = 0; kk < 4; kk++) {
                uint32_t bf[4];
                const int row = j2*16 + ((g & 2) << 2) + (lane & 7);
                const int chunk = kk*2 + (g & 1);
                ldsm4(bf, kb + row*128 + ((chunk ^ (row & 7))*16));
#pragma unroll
                for (int mi = 0; mi < 2; mi++) {
                    mma16816(s0[mi], qa[mi][kk], bf[0], bf[1]);
                    mma16816(s1[mi], qa[mi][kk], bf[2], bf[3]);
                }
            }
            {
                const float a0 = fexp2(s0[0][0]);
                const float a1 = fexp2(s0[0][1]);
                const float a2 = fexp2(s0[0][2]);
                const float a3 = fexp2(s0[0][3]);
                rA0 += a0 + a1; rB0 += a2 + a3;
                pa[0][j2][0] = pack_f16x2(a0, a1);
                pa[0][j2][1] = pack_f16x2(a2, a3);
                const float b0 = fexp2(s1[0][0]);
                const float b1 = fexp2(s1[0][1]);
                const float b2 = fexp2(s1[0][2]);
                const float b3 = fexp2(s1[0][3]);
                rA0 += b0 + b1; rB0 += b2 + b3;
                pa[0][j2][2] = pack_f16x2(b0, b1);
                pa[0][j2][3] = pack_f16x2(b2, b3);
            }
            {
                const float a0 = fexp2(s0[1][0]);
                const float a1 = fexp2(s0[1][1]);
                const float a2 = fexp2(s0[1][2]);
                const float a3 = fexp2(s0[1][3]);
                rA1 += a0 + a1; rB1 += a2 + a3;
                pa[1][j2][0] = pack_f16x2(a0, a1);
                pa[1][j2][1] = pack_f16x2(a2, a3);
                const float b0 = fexp2(s1[1][0]);
                const float b1 = fexp2(s1[1][1]);
                const float b2 = fexp2(s1[1][2]);
                const float b3 = fexp2(s1[1][3]);
                rA1 += b0 + b1; rB1 += b2 + b3;
                pa[1][j2][2] = pack_f16x2(b0, b1);
                pa[1][j2][3] = pack_f16x2(b2, b3);
            }
        }
        rA0 += __shfl_xor_sync(0xffffffffu, rA0, 1);
        rA0 += __shfl_xor_sync(0xffffffffu, rA0, 2);
        rB0 += __shfl_xor_sync(0xffffffffu, rB0, 1);
        rB0 += __shfl_xor_sync(0xffffffffu, rB0, 2);
        rA1 += __shfl_xor_sync(0xffffffffu, rA1, 1);
        rA1 += __shfl_xor_sync(0xffffffffu, rA1, 2);
        rB1 += __shfl_xor_sync(0xffffffffu, rB1, 1);
        rB1 += __shfl_xor_sync(0xffffffffu, rB1, 2);
        lA0 += rA0; lB0 += rB0; lA1 += rA1; lB1 += rB1;

        // ---- O += P @ V : each vf feeds 4 MMAs (2 mi) ----
#pragma unroll
        for (int kk = 0; kk < 4; kk++) {
#pragma unroll
            for (int j2 = 0; j2 < 4; j2++) {
                uint32_t vf[4];
                const int row = kk*16 + ((g & 1) << 3) + (lane & 7);
                const int chunk = j2*2 + (g >> 1);
                ldsm4t(vf, vb + row*128 + ((chunk ^ (row & 7))*16));
#pragma unroll
                for (int mi = 0; mi < 2; mi++) {
                    mma16816(oacc[mi][2*j2],   pa[mi][kk], vf[0], vf[1]);
                    mma16816(oacc[mi][2*j2+1], pa[mi][kk], vf[2], vf[3]);
                }
            }
        }

        buf = (buf == 2) ? 0 : buf + 1;
    }

    // epilogue: scale by gate/l, write fp16 g_atth [b][n][h*64+d]
#pragma unroll
    for (int mi = 0; mi < 2; mi++) {
        const float lA = (mi == 0) ? lA0 : lA1;
        const float lB = (mi == 0) ? lB0 : lB1;
        const int r1 = w*32 + mi*16 + (lane >> 2);
        const int r2 = r1 + 8;
        const int n1 = qt*128 + r1;
        const int n2 = qt*128 + r2;
        const float f1 = g_gates[((size_t)(b*NN + n1))*HH + head] / lA;
        const float f2 = g_gates[((size_t)(b*NN + n2))*HH + head] / lB;
        __half* O1 = g_atth + ((size_t)(b*NN + n1))*INNER + head*DHD + 2*(lane & 3);
        __half* O2 = g_atth + ((size_t)(b*NN + n2))*INNER + head*DHD + 2*(lane & 3);
#pragma unroll
        for (int j = 0; j < 8; j++) {
            *(__half2*)(O1 + j*8) = __floats2half2_rn(oacc[mi][j][0]*f1, oacc[mi][j][1]*f1);
            *(__half2*)(O2 + j*8) = __floats2half2_rn(oacc[mi][j][2]*f2, oacc[mi][j][3]*f2);
        }
    }
}

// ---------------------------------------------------------------------------
// K4: HMMA GEMM Out = g_atth[8192,512] @ Wouth[512,512] + bias
// BM=128 BN=64 BK=64, static SMEM 48KB
// ---------------------------------------------------------------------------
__global__ __launch_bounds__(256, 2) void out_hmma(
    const float* __restrict__ bias, float* __restrict__ Out)
{
    __shared__ __align__(128) __half smA[2*128*64];
    __shared__ __align__(128) __half smB[2*64*64];

    const int tid = threadIdx.x;
    const int lane = tid & 31;
    const int w = tid >> 5;
    const int wm = w & 3;
    const int wn = w >> 2;
    const int tileM = blockIdx.y * 128;
    const int tileN = blockIdx.x * 64;

    const uint32_t sa = smem_u32(smA);
    const uint32_t sbm = smem_u32(smB);
    const __half* A = g_atth;
    const __half* B = g_wouth;

#pragma unroll
    for (int t = 0; t < 2; t++) {
#pragma unroll
        for (int i = 0; i < 4; i++) {
            const int idx = tid + i*256;
            const int r = idx >> 3, c = idx & 7;
            cp16(sa + t*16384 + r*128 + ((c ^ (r & 7))*16),
                 A + (size_t)(tileM + r)*INNER + t*64 + c*8);
        }
#pragma unroll
        for (int i = 0; i < 2; i++) {
            const int idx = tid + i*256;
            const int r = idx >> 3, c = idx & 7;
            cp16(sbm + t*8192 + r*128 + ((c ^ (r & 7))*16),
                 B + (size_t)(t*64 + r)*DD + tileN + c*8);
        }
        CP_COMMIT();
    }

    float acc[2][4][4];
#pragma unroll
    for (int mi = 0; mi < 2; mi++)
#pragma unroll
        for (int ni = 0; ni < 4; ni++)
#pragma unroll
            for (int i = 0; i < 4; i++) acc[mi][ni][i] = 0.f;

    for (int it = 0; it < INNER/64; it++) {
        const int buf = it & 1;
        CP_WAIT1();
        __syncthreads();
        const uint32_t ka = sa + buf*16384;
        const uint32_t kb = sbm + buf*8192;

#pragma unroll
        for (int kk = 0; kk < 4; kk++) {
            uint32_t a[2][4];
            const int g = lane >> 3;
#pragma unroll
            for (int mi = 0; mi < 2; mi++) {
                const int row = wm*32 + mi*16 + (lane & 7) + ((g & 1) << 3);
                const int chunk = kk*2 + (g >> 1);
                ldsm4(a[mi], ka + row*128 + ((chunk ^ (row & 7))*16));
            }
#pragma unroll
            for (int j2 = 0; j2 < 2; j2++) {
                uint32_t bf[4];
                const int row = kk*16 + ((g & 1) << 3) + (lane & 7);
                const int chunk = wn*4 + j2*2 + (g >> 1);
                ldsm4t(bf, kb + row*128 + ((chunk ^ (row & 7))*16));
#pragma unroll
                for (int mi = 0; mi < 2; mi++) {
                    mma16816(acc[mi][2*j2],   a[mi], bf[0], bf[1]);
                    mma16816(acc[mi][2*j2+1], a[mi], bf[2], bf[3]);
                }
            }
        }

        __syncthreads();
        if (it + 2 < INNER/64) {
#pragma unroll
            for (int i = 0; i < 4; i++) {
                const int idx = tid + i*256;
                const int r = idx >> 3, c = idx & 7;
                cp16(sa + buf*16384 + r*128 + ((c ^ (r & 7))*16),
                     A + (size_t)(tileM + r)*INNER + (it+2)*64 + c*8);
            }
#pragma unroll
            for (int i = 0; i < 2; i++) {
                const int idx = tid + i*256;
                const int r = idx >> 3, c = idx & 7;
                cp16(sbm + buf*8192 + r*128 + ((c ^ (r & 7))*16),
                     B + (size_t)((it+2)*64 + r)*DD + tileN + c*8);
            }
        }
        CP_COMMIT();
    }

#pragma unroll
    for (int mi = 0; mi < 2; mi++) {
        const int r1 = tileM + wm*32 + mi*16 + (lane >> 2);
#pragma unroll
        for (int ni = 0; ni < 4; ni++) {
            const int c0 = tileN + wn*32 + ni*8 + 2*(lane & 3);
            const float b0 = bias[c0];
            const float b1 = bias[c0+1];
#pragma unroll
            for (int rr = 0; rr < 2; rr++) {
                const int row = r1 + rr*8;
                *(float2*)(Out + (size_t)row*DD + c0) =
                    make_float2(acc[mi][ni][2*rr] + b0, acc[mi][ni][2*rr+1] + b1);
            }
        }
    }
}

// ---------------------------------------------------------------------------
extern "C" void kernel_launch(void* const* d_in, const int* in_sizes, int n_in,
                              void* d_out, int out_size)
{
    const float* x       = (const float*)d_in[0];
    const float* w_qkv   = (const float*)d_in[1];
    const float* w_gates = (const float*)d_in[2];
    const float* b_gates = (const float*)d_in[3];
    const float* w_out   = (const float*)d_in[4];
    const float* b_out   = (const float*)d_in[5];
    float* out = (float*)d_out;

    cudaFuncSetAttribute(qkv_hmma, cudaFuncAttributeMaxDynamicSharedMemorySize, 65536);

    // flash_hmma stays the 4th launch (ncu capture slot)
    prep_all<<<(NCVT + NROPE + 255)/256, 256>>>(x, w_qkv, w_out);      // 0
    gates_kernel<<<BNROWS/8, 256>>>(x, w_gates, b_gates);              // 1

    dim3 g1(QKVC/128, BNROWS/128);       // 12 x 64
    qkv_hmma<<<g1, 256, 65536>>>();                                    // 2

    dim3 g3(NN/128, BB*HH);              // 32 x 16
    flash_hmma<<<g3, 128>>>();                                         // 3

    dim3 g4(DD/64, BNROWS/128);          // 8 x 64
    out_hmma<<<g4, 256>>>(b_out, out);                                 // 4
}

// round 15
// speedup vs baseline: 1.5379x; 1.5379x over previous
#include <cuda_runtime.h>
#include <cuda_fp16.h>
#include <math.h>
#include <stdint.h>

#define BB 2
#define NN 4096
#define DD 512
#define HH 8
#define DHD 64
#define BNROWS (BB*NN)        // 8192
#define QKVC (3*HH*DHD)       // 1536
#define INNER (HH*DHD)        // 512

// Scratch (device globals; no allocations allowed)
__device__ __align__(16) __half g_xh[BNROWS*DD];      // x in fp16
__device__ __align__(16) __half g_wqkvh[DD*QKVC];     // w_qkv in fp16
__device__ __align__(16) __half g_wouth[INNER*DD];    // w_out in fp16
__device__ __align__(16) __half g_qh[BB*HH*NN*DHD];   // [bh][n][64], pre-scaled by 0.125*log2e
__device__ __align__(16) __half g_kh[BB*HH*NN*DHD];   // [bh][n][64]
__device__ __align__(16) __half g_vh[BB*HH*NN*DHD];   // [bh][n][64]
__device__ __align__(16) __half g_atth[BNROWS*INNER]; // attention output fp16 [b][n][h*64+d]
__device__ __align__(16) float g_gates[BNROWS*HH];
__device__ __align__(16) float g_cost[NN*16];
__device__ __align__(16) float g_sint[NN*16];

// inv_freq[j] = 10^(-j/16), j = 0..15
__constant__ float c_invf[16] = {
    1.0000000000f, 0.8659643234f, 0.7498942093f, 0.6493816316f,
    0.5623413252f, 0.4869675252f, 0.4216965034f, 0.3651741273f,
    0.3162277660f, 0.2738419634f, 0.2371373706f, 0.2053525026f,
    0.1778279410f, 0.1539926526f, 0.1333521432f, 0.1154781985f
};

#define QSCALE 0.1803368801111831f   /* 0.125 * log2(e): S comes out in log2 units */
#define SHIFT2 11.541560327111707f   /* 8 * log2(e): static softmax shift */

// ---------------------------------------------------------------------------
// helpers
// ---------------------------------------------------------------------------
__device__ __forceinline__ uint32_t smem_u32(const void* p) {
    uint32_t a;
    asm("{ .reg .u64 t; cvta.to.shared.u64 t, %1; cvt.u32.u64 %0, t; }" : "=r"(a) : "l"(p));
    return a;
}
__device__ __forceinline__ float fexp2(float x) {
    float r; asm("ex2.approx.f32 %0, %1;" : "=f"(r) : "f"(x)); return r;
}
__device__ __forceinline__ uint32_t pack_f16x2(float lo, float hi) {
    uint32_t r; asm("cvt.rn.f16x2.f32 %0, %1, %2;" : "=r"(r) : "f"(hi), "f"(lo)); return r;
}
__device__ __forceinline__ void ldsm4(uint32_t r[4], uint32_t addr) {
    asm volatile("ldmatrix.sync.aligned.m8n8.x4.shared.b16 {%0,%1,%2,%3}, [%4];"
        : "=r"(r[0]), "=r"(r[1]), "=r"(r[2]), "=r"(r[3]) : "r"(addr));
}
__device__ __forceinline__ void ldsm4t(uint32_t r[4], uint32_t addr) {
    asm volatile("ldmatrix.sync.aligned.m8n8.x4.trans.shared.b16 {%0,%1,%2,%3}, [%4];"
        : "=r"(r[0]), "=r"(r[1]), "=r"(r[2]), "=r"(r[3]) : "r"(addr));
}
__device__ __forceinline__ void mma16816(float* c, const uint32_t* a, uint32_t b0, uint32_t b1) {
    asm volatile("mma.sync.aligned.m16n8k16.row.col.f32.f16.f16.f32 "
        "{%0,%1,%2,%3}, {%4,%5,%6,%7}, {%8,%9}, {%0,%1,%2,%3};"
        : "+f"(c[0]), "+f"(c[1]), "+f"(c[2]), "+f"(c[3])
        : "r"(a[0]), "r"(a[1]), "r"(a[2]), "r"(a[3]), "r"(b0), "r"(b1));
}
__device__ __forceinline__ void cp16(uint32_t dst, const void* src) {
    asm volatile("cp.async.cg.shared.global [%0], [%1], 16;" :: "r"(dst), "l"(src));
}
#define CP_COMMIT() asm volatile("cp.async.commit_group;" ::: "memory")
#define CP_WAIT1()  asm volatile("cp.async.wait_group 1;" ::: "memory")

// ---------------------------------------------------------------------------
// K0: fused prep — fp32->fp16 for x, w_qkv, w_out + RoPE tables, one launch
// ---------------------------------------------------------------------------
#define N1_4 (BNROWS*DD/4)    // 1048576
#define N2_4 (DD*QKVC/4)      //  196608
#define N3_4 (INNER*DD/4)     //   65536
#define NCVT (N1_4 + N2_4 + N3_4)
#define NROPE (NN*16)         //   65536

__global__ __launch_bounds__(256) void prep_all(
    const float* __restrict__ x, const float* __restrict__ wq,
    const float* __restrict__ wo)
{
    const int i = blockIdx.x * 256 + threadIdx.x;
    if (i < NCVT) {
        const float* src;
        __half* dst;
        int off;
        if (i < N1_4) { src = x; dst = g_xh; off = i; }
        else if (i < N1_4 + N2_4) { src = wq; dst = g_wqkvh; off = i - N1_4; }
        else { src = wo; dst = g_wouth; off = i - N1_4 - N2_4; }
        float4 v = ((const float4*)src)[off];
        uint2 o;
        o.x = pack_f16x2(v.x, v.y);
        o.y = pack_f16x2(v.z, v.w);
        ((uint2*)dst)[off] = o;
    } else {
        const int idx = i - NCVT;
        if (idx < NROPE) {
            const int n = idx >> 4;
            const int p = idx & 15;
            float s, c;
            sincosf((float)n * c_invf[p], &s, &c);
            g_cost[idx] = c;
            g_sint[idx] = s;
        }
    }
}

// ---------------------------------------------------------------------------
// K2: gates = sigmoid(X @ Wg + bg)  (fp32 — reads harness x directly)
// ---------------------------------------------------------------------------
__global__ __launch_bounds__(256) void gates_kernel(
    const float* __restrict__ X, const float* __restrict__ Wg,
    const float* __restrict__ bg)
{
    const int warp = threadIdx.x >> 5;
    const int lane = threadIdx.x & 31;
    const int row = blockIdx.x * 8 + warp;

    float p[8];
#pragma unroll
    for (int h = 0; h < 8; h++) p[h] = 0.f;

    for (int d = lane; d < DD; d += 32) {
        const float xv = X[(size_t)row*DD + d];
        const float* wr = Wg + (size_t)d*HH;
#pragma unroll
        for (int h = 0; h < 8; h++) p[h] = fmaf(xv, wr[h], p[h]);
    }
#pragma unroll
    for (int h = 0; h < 8; h++) {
#pragma unroll
        for (int off = 16; off > 0; off >>= 1)
            p[h] += __shfl_down_sync(0xffffffffu, p[h], off);
    }
    if (lane == 0) {
#pragma unroll
        for (int h = 0; h < 8; h++) {
            const float z = p[h] + bg[h];
            g_gates[(size_t)row*HH + h] = 1.f / (1.f + expf(-z));
        }
    }
}

// ---------------------------------------------------------------------------
// K1: HMMA GEMM QKV = Xh[8192,512] @ Wh[512,1536] with fused RoPE epilogue.
// BM=128 BN=128 BK=64, 256 threads. Dynamic SMEM 64KB.
// ---------------------------------------------------------------------------
__global__ __launch_bounds__(256, 2) void qkv_hmma()
{
    extern __shared__ __align__(128) __half dsm[];
    const int tid = threadIdx.x;
    const int lane = tid & 31;
    const int w = tid >> 5;
    const int wm = w & 3;
    const int wn = w >> 2;
    const int tileM = blockIdx.y * 128;
    const int tileN = blockIdx.x * 128;

    const uint32_t sa = smem_u32(dsm);
    const uint32_t sbm = sa + 32768;
    const __half* A = g_xh;
    const __half* B = g_wqkvh;

#pragma unroll
    for (int t = 0; t < 2; t++) {
#pragma unroll
        for (int i = 0; i < 4; i++) {
            const int idx = tid + i*256;
            const int r = idx >> 3, c = idx & 7;
            cp16(sa + t*16384 + r*128 + ((c ^ (r & 7))*16),
                 A + (size_t)(tileM + r)*DD + t*64 + c*8);
        }
#pragma unroll
        for (int i = 0; i < 4; i++) {
            const int idx = tid + i*256;
            const int r = idx >> 4, c = idx & 15;
            cp16(sbm + t*16384 + r*256 + ((c ^ (r & 7))*16),
                 B + (size_t)(t*64 + r)*QKVC + tileN + c*8);
        }
        CP_COMMIT();
    }

    float acc[2][8][4];
#pragma unroll
    for (int mi = 0; mi < 2; mi++)
#pragma unroll
        for (int ni = 0; ni < 8; ni++)
#pragma unroll
            for (int i = 0; i < 4; i++) acc[mi][ni][i] = 0.f;

    for (int it = 0; it < DD/64; it++) {
        const int buf = it & 1;
        CP_WAIT1();
        __syncthreads();
        const uint32_t ka = sa + buf*16384;
        const uint32_t kb = sbm + buf*16384;

#pragma unroll
        for (int kk = 0; kk < 4; kk++) {
            uint32_t a[2][4];
            const int g = lane >> 3;
#pragma unroll
            for (int mi = 0; mi < 2; mi++) {
                const int row = wm*32 + mi*16 + (lane & 7) + ((g & 1) << 3);
                const int chunk = kk*2 + (g >> 1);
                ldsm4(a[mi], ka + row*128 + ((chunk ^ (row & 7))*16));
            }
#pragma unroll
            for (int j2 = 0; j2 < 4; j2++) {
                uint32_t bf[4];
                const int row = kk*16 + ((g & 1) << 3) + (lane & 7);
                const int chunk = wn*8 + j2*2 + (g >> 1);
                ldsm4t(bf, kb + row*256 + ((chunk ^ (row & 7))*16));
#pragma unroll
                for (int mi = 0; mi < 2; mi++) {
                    mma16816(acc[mi][2*j2],   a[mi], bf[0], bf[1]);
                    mma16816(acc[mi][2*j2+1], a[mi], bf[2], bf[3]);
                }
            }
        }

        __syncthreads();
        if (it + 2 < DD/64) {
#pragma unroll
            for (int i = 0; i < 4; i++) {
                const int idx = tid + i*256;
                const int r = idx >> 3, c = idx & 7;
                cp16(sa + buf*16384 + r*128 + ((c ^ (r & 7))*16),
                     A + (size_t)(tileM + r)*DD + (it+2)*64 + c*8);
            }
#pragma unroll
            for (int i = 0; i < 4; i++) {
                const int idx = tid + i*256;
                const int r = idx >> 4, c = idx & 15;
                cp16(sbm + buf*16384 + r*256 + ((c ^ (r & 7))*16),
                     B + (size_t)((it+2)*64 + r)*QKVC + tileN + c*8);
            }
        }
        CP_COMMIT();
    }

    // ---- epilogue: RoPE + scatter to fp16 q/k/v ----
#pragma unroll
    for (int mi = 0; mi < 2; mi++) {
        const int r1 = tileM + wm*32 + mi*16 + (lane >> 2);
#pragma unroll
        for (int ni = 0; ni < 8; ni++) {
            const int c0 = tileN + wn*64 + ni*8 + 2*(lane & 3);
            const int which = c0 >> 9;       // 0=q, 1=k, 2=v
            const int rem = c0 & 511;
            const int head = rem >> 6;
            const int dd = rem & 63;         // even
            const int p = (dd >> 1) & 15;
#pragma unroll
            for (int rr = 0; rr < 2; rr++) {
                const int row = r1 + rr*8;
                const int b = row >> 12;
                const int n = row & 4095;
                const float v1 = acc[mi][ni][2*rr];
                const float v2 = acc[mi][ni][2*rr+1];
                const size_t base = (((size_t)(b*HH + head))*NN + n)*DHD + dd;
                if (which == 2) {
                    *(__half2*)(g_vh + base) = __floats2half2_rn(v1, v2);
                } else {
                    const float cs = g_cost[n*16 + p];
                    const float sn = g_sint[n*16 + p];
                    const float o1 = v1*cs - v2*sn;
                    const float o2 = v1*sn + v2*cs;
                    if (which == 0)
                        *(__half2*)(g_qh + base) = __floats2half2_rn(o1*QSCALE, o2*QSCALE);
                    else
                        *(__half2*)(g_kh + base) = __floats2half2_rn(o1, o2);
                }
            }
        }
    }
}

// ---------------------------------------------------------------------------
// K3: HMMA flash attention — 4 warps x 32 query rows, 3-buffer cp.async ring
// with ONE __syncthreads per iteration. Softmax shift folded into S init.
// 48KB static smem, 2 CTAs/SM.
// ---------------------------------------------------------------------------
__global__ __launch_bounds__(128, 2) void flash_hmma()
{
    __shared__ __align__(128) __half smem[6*4096];   // 48 KB: 3 x (K 8KB | V 8KB)

    const int tid = threadIdx.x;
    const int lane = tid & 31;
    const int w = tid >> 5;          // 0..3, each owns 32 query rows
    const int bh = blockIdx.y;
    const int b = bh >> 3;
    const int head = bh & 7;
    const int qt = blockIdx.x;

    const __half* Qg = g_qh + ((size_t)bh*NN + qt*128)*DHD;
    const __half* Kg = g_kh + (size_t)bh*NN*DHD;
    const __half* Vg = g_vh + (size_t)bh*NN*DHD;

    const uint32_t sb = smem_u32(smem);

    // stage Q tile [128x64] (swizzled, into buf0 region), extract A-fragments
#pragma unroll
    for (int i = 0; i < 8; i++) {
        const int idx = tid + i*128;          // 0..1023
        const int row = idx >> 3;
        const int c = idx & 7;
        float4 val = *(const float4*)(Qg + row*DHD + c*8);
        *(float4*)((char*)smem + row*128 + ((c ^ (row & 7))*16)) = val;
    }
    __syncthreads();

    uint32_t qa[2][4][4];
    {
        const int g = lane >> 3;
#pragma unroll
        for (int mi = 0; mi < 2; mi++) {
#pragma unroll
            for (int kk = 0; kk < 4; kk++) {
                const int row = w*32 + mi*16 + (lane & 7) + ((g & 1) << 3);
                const int chunk = kk*2 + (g >> 1);
                ldsm4(qa[mi][kk], sb + row*128 + ((chunk ^ (row & 7))*16));
            }
        }
    }
    __syncthreads();

    // prefetch key-tiles 0,1 into bufs 0,1
#pragma unroll
    for (int t = 0; t < 2; t++) {
#pragma unroll
        for (int i = 0; i < 8; i++) {
            const int idx = tid + i*128;       // 0..1023
            const int isV = idx >> 9;
            const int r = (idx & 511) >> 3;
            const int c = idx & 7;
            const __half* src = (isV ? Vg : Kg) + ((size_t)t*64 + r)*DHD + c*8;
            const uint32_t dst = sb + t*16384 + isV*8192 + r*128 + ((c ^ (r & 7))*16);
            cp16(dst, src);
        }
        CP_COMMIT();
    }

    float oacc[2][8][4];
#pragma unroll
    for (int mi = 0; mi < 2; mi++)
#pragma unroll
        for (int j = 0; j < 8; j++)
#pragma unroll
            for (int i = 0; i < 4; i++) oacc[mi][j][i] = 0.f;
    float lA0 = 0.f, lB0 = 0.f, lA1 = 0.f, lB1 = 0.f;

    int buf = 0;
    for (int it = 0; it < NN/64; it++) {
        __syncthreads();      // all warps done reading buf (it-1)%3
        CP_WAIT1();           // tile it has landed
        // prefetch tile it+2 into buf (it+2)%3 == (it-1)%3 — safe post-barrier
        if (it + 2 < NN/64) {
            const int pbuf = (buf + 2 > 2) ? buf - 1 : buf + 2;
#pragma unroll
            for (int i = 0; i < 8; i++) {
                const int idx = tid + i*128;
                const int isV = idx >> 9;
                const int r = (idx & 511) >> 3;
                const int c = idx & 7;
                const __half* src = (isV ? Vg : Kg) + ((size_t)(it+2)*64 + r)*DHD + c*8;
                const uint32_t dst = sb + pbuf*16384 + isV*8192 + r*128 + ((c ^ (r & 7))*16);
                cp16(dst, src);
            }
        }
        CP_COMMIT();

        const uint32_t kb = sb + buf*16384;
        const uint32_t vb = kb + 8192;

        // ---- fused QK + softmax, j2-outer; shift folded into accum init ----
        uint32_t pa[2][4][4];
        float rA0 = 0.f, rB0 = 0.f, rA1 = 0.f, rB1 = 0.f;
        const int g = lane >> 3;
#pragma unroll
        for (int j2 = 0; j2 < 4; j2++) {
            float s0[2][4], s1[2][4];
#pragma unroll
            for (int mi = 0; mi < 2; mi++)
#pragma unroll
                for (int i = 0; i < 4; i++) { s0[mi][i] = -SHIFT2; s1[mi][i] = -SHIFT2; }
#pragma unroll
            for (int kk = 0; kk < 4; kk++) {
                uint32_t bf[4];
                const int row = j2*16 + ((g & 2) << 2) + (lane & 7);
                const int chunk = kk*2 + (g & 1);
                ldsm4(bf, kb + row*128 + ((chunk ^ (row & 7))*16));
#pragma unroll
                for (int mi = 0; mi < 2; mi++) {
                    mma16816(s0[mi], qa[mi][kk], bf[0], bf[1]);
                    mma16816(s1[mi], qa[mi][kk], bf[2], bf[3]);
                }
            }
            {
                const float a0 = fexp2(s0[0][0]);
                const float a1 = fexp2(s0[0][1]);
                const float a2 = fexp2(s0[0][2]);
                const float a3 = fexp2(s0[0][3]);
                rA0 += a0 + a1; rB0 += a2 + a3;
                pa[0][j2][0] = pack_f16x2(a0, a1);
                pa[0][j2][1] = pack_f16x2(a2, a3);
                const float b0 = fexp2(s1[0][0]);
                const float b1 = fexp2(s1[0][1]);
                const float b2 = fexp2(s1[0][2]);
                const float b3 = fexp2(s1[0][3]);
                rA0 += b0 + b1; rB0 += b2 + b3;
                pa[0][j2][2] = pack_f16x2(b0, b1);
                pa[0][j2][3] = pack_f16x2(b2, b3);
            }
            {
                const float a0 = fexp2(s0[1][0]);
                const float a1 = fexp2(s0[1][1]);
                const float a2 = fexp2(s0[1][2]);
                const float a3 = fexp2(s0[1][3]);
                rA1 += a0 + a1; rB1 += a2 + a3;
                pa[1][j2][0] = pack_f16x2(a0, a1);
                pa[1][j2][1] = pack_f16x2(a2, a3);
                const float b0 = fexp2(s1[1][0]);
                const float b1 = fexp2(s1[1][1]);
                const float b2 = fexp2(s1[1][2]);
                const float b3 = fexp2(s1[1][3]);
                rA1 += b0 + b1; rB1 += b2 + b3;
                pa[1][j2][2] = pack_f16x2(b0, b1);
                pa[1][j2][3] = pack_f16x2(b2, b3);
            }
        }
        rA0 += __shfl_xor_sync(0xffffffffu, rA0, 1);
        rA0 += __shfl_xor_sync(0xffffffffu, rA0, 2);
        rB0 += __shfl_xor_sync(0xffffffffu, rB0, 1);
        rB0 += __shfl_xor_sync(0xffffffffu, rB0, 2);
        rA1 += __shfl_xor_sync(0xffffffffu, rA1, 1);
        rA1 += __shfl_xor_sync(0xffffffffu, rA1, 2);
        rB1 += __shfl_xor_sync(0xffffffffu, rB1, 1);
        rB1 += __shfl_xor_sync(0xffffffffu, rB1, 2);
        lA0 += rA0; lB0 += rB0; lA1 += rA1; lB1 += rB1;

        // ---- O += P @ V : each vf feeds 4 MMAs (2 mi) ----
#pragma unroll
        for (int kk = 0; kk < 4; kk++) {
#pragma unroll
            for (int j2 = 0; j2 < 4; j2++) {
                uint32_t vf[4];
                const int row = kk*16 + ((g & 1) << 3) + (lane & 7);
                const int chunk = j2*2 + (g >> 1);
                ldsm4t(vf, vb + row*128 + ((chunk ^ (row & 7))*16));
#pragma unroll
                for (int mi = 0; mi < 2; mi++) {
                    mma16816(oacc[mi][2*j2],   pa[mi][kk], vf[0], vf[1]);
                    mma16816(oacc[mi][2*j2+1], pa[mi][kk], vf[2], vf[3]);
                }
            }
        }

        buf = (buf == 2) ? 0 : buf + 1;
    }

    // epilogue: scale by gate/l, write fp16 g_atth [b][n][h*64+d]
#pragma unroll
    for (int mi = 0; mi < 2; mi++) {
        const float lA = (mi == 0) ? lA0 : lA1;
        const float lB = (mi == 0) ? lB0 : lB1;
        const int r1 = w*32 + mi*16 + (lane >> 2);
        const int r2 = r1 + 8;
        const int n1 = qt*128 + r1;
        const int n2 = qt*128 + r2;
        const float f1 = g_gates[((size_t)(b*NN + n1))*HH + head] / lA;
        const float f2 = g_gates[((size_t)(b*NN + n2))*HH + head] / lB;
        __half* O1 = g_atth + ((size_t)(b*NN + n1))*INNER + head*DHD + 2*(lane & 3);
        __half* O2 = g_atth + ((size_t)(b*NN + n2))*INNER + head*DHD + 2*(lane & 3);
#pragma unroll
        for (int j = 0; j < 8; j++) {
            *(__half2*)(O1 + j*8) = __floats2half2_rn(oacc[mi][j][0]*f1, oacc[mi][j][1]*f1);
            *(__half2*)(O2 + j*8) = __floats2half2_rn(oacc[mi][j][2]*f2, oacc[mi][j][3]*f2);
        }
    }
}

// ---------------------------------------------------------------------------
// K4: HMMA GEMM Out = g_atth[8192,512] @ Wouth[512,512] + bias
// BM=128 BN=64 BK=64, static SMEM 48KB
// ---------------------------------------------------------------------------
__global__ __launch_bounds__(256, 2) void out_hmma(
    const float* __restrict__ bias, float* __restrict__ Out)
{
    __shared__ __align__(128) __half smA[2*128*64];
    __shared__ __align__(128) __half smB[2*64*64];

    const int tid = threadIdx.x;
    const int lane = tid & 31;
    const int w = tid >> 5;
    const int wm = w & 3;
    const int wn = w >> 2;
    const int tileM = blockIdx.y * 128;
    const int tileN = blockIdx.x * 64;

    const uint32_t sa = smem_u32(smA);
    const uint32_t sbm = smem_u32(smB);
    const __half* A = g_atth;
    const __half* B = g_wouth;

#pragma unroll
    for (int t = 0; t < 2; t++) {
#pragma unroll
        for (int i = 0; i < 4; i++) {
            const int idx = tid + i*256;
            const int r = idx >> 3, c = idx & 7;
            cp16(sa + t*16384 + r*128 + ((c ^ (r & 7))*16),
                 A + (size_t)(tileM + r)*INNER + t*64 + c*8);
        }
#pragma unroll
        for (int i = 0; i < 2; i++) {
            const int idx = tid + i*256;
            const int r = idx >> 3, c = idx & 7;
            cp16(sbm + t*8192 + r*128 + ((c ^ (r & 7))*16),
                 B + (size_t)(t*64 + r)*DD + tileN + c*8);
        }
        CP_COMMIT();
    }

    float acc[2][4][4];
#pragma unroll
    for (int mi = 0; mi < 2; mi++)
#pragma unroll
        for (int ni = 0; ni < 4; ni++)
#pragma unroll
            for (int i = 0; i < 4; i++) acc[mi][ni][i] = 0.f;

    for (int it = 0; it < INNER/64; it++) {
        const int buf = it & 1;
        CP_WAIT1();
        __syncthreads();
        const uint32_t ka = sa + buf*16384;
        const uint32_t kb = sbm + buf*8192;

#pragma unroll
        for (int kk = 0; kk < 4; kk++) {
            uint32_t a[2][4];
            const int g = lane >> 3;
#pragma unroll
            for (int mi = 0; mi < 2; mi++) {
                const int row = wm*32 + mi*16 + (lane & 7) + ((g & 1) << 3);
                const int chunk = kk*2 + (g >> 1);
                ldsm4(a[mi], ka + row*128 + ((chunk ^ (row & 7))*16));
            }
#pragma unroll
            for (int j2 = 0; j2 < 2; j2++) {
                uint32_t bf[4];
                const int row = kk*16 + ((g & 1) << 3) + (lane & 7);
                const int chunk = wn*4 + j2*2 + (g >> 1);
                ldsm4t(bf, kb + row*128 + ((chunk ^ (row & 7))*16));
#pragma unroll
                for (int mi = 0; mi < 2; mi++) {
                    mma16816(acc[mi][2*j2],   a[mi], bf[0], bf[1]);
                    mma16816(acc[mi][2*j2+1], a[mi], bf[2], bf[3]);
                }
            }
        }

        __syncthreads();
        if (it + 2 < INNER/64) {
#pragma unroll
            for (int i = 0; i < 4; i++) {
                const int idx = tid + i*256;
                const int r = idx >> 3, c = idx & 7;
                cp16(sa + buf*16384 + r*128 + ((c ^ (r & 7))*16),
                     A + (size_t)(tileM + r)*INNER + (it+2)*64 + c*8);
            }
#pragma unroll
            for (int i = 0; i < 2; i++) {
                const int idx = tid + i*256;
                const int r = idx >> 3, c = idx & 7;
                cp16(sbm + buf*8192 + r*128 + ((c ^ (r & 7))*16),
                     B + (size_t)((it+2)*64 + r)*DD + tileN + c*8);
            }
        }
        CP_COMMIT();
    }

#pragma unroll
    for (int mi = 0; mi < 2; mi++) {
        const int r1 = tileM + wm*32 + mi*16 + (lane >> 2);
#pragma unroll
        for (int ni = 0; ni < 4; ni++) {
            const int c0 = tileN + wn*32 + ni*8 + 2*(lane & 3);
            const float b0 = bias[c0];
            const float b1 = bias[c0+1];
#pragma unroll
            for (int rr = 0; rr < 2; rr++) {
                const int row = r1 + rr*8;
                *(float2*)(Out + (size_t)row*DD + c0) =
                    make_float2(acc[mi][ni][2*rr] + b0, acc[mi][ni][2*rr+1] + b1);
            }
        }
    }
}

// ---------------------------------------------------------------------------
extern "C" void kernel_launch(void* const* d_in, const int* in_sizes, int n_in,
                              void* d_out, int out_size)
{
    const float* x       = (const float*)d_in[0];
    const float* w_qkv   = (const float*)d_in[1];
    const float* w_gates = (const float*)d_in[2];
    const float* b_gates = (const float*)d_in[3];
    const float* w_out   = (const float*)d_in[4];
    const float* b_out   = (const float*)d_in[5];
    float* out = (float*)d_out;

    cudaFuncSetAttribute(qkv_hmma, cudaFuncAttributeMaxDynamicSharedMemorySize, 65536);

    // flash_hmma stays the 4th launch (ncu capture slot)
    prep_all<<<(NCVT + NROPE + 255)/256, 256>>>(x, w_qkv, w_out);      // 0
    gates_kernel<<<BNROWS/8, 256>>>(x, w_gates, b_gates);              // 1

    dim3 g1(QKVC/128, BNROWS/128);       // 12 x 64
    qkv_hmma<<<g1, 256, 65536>>>();                                    // 2

    dim3 g3(NN/128, BB*HH);              // 32 x 16
    flash_hmma<<<g3, 128>>>();                                         // 3

    dim3 g4(DD/64, BNROWS/128);          // 8 x 64
    out_hmma<<<g4, 256>>>(b_out, out);                                 // 4
}